// round 1
// baseline (speedup 1.0000x reference)
#include <cuda_runtime.h>

// Problem constants
static constexpr int B_DIM = 256;
static constexpr int N_DIM = 65536;
static constexpr int BN    = B_DIM * N_DIM;          // 16,777,216
static constexpr int BN4   = BN / 4;                 // float4 count per tensor
static constexpr int N4    = N_DIM / 4;              // float4 count in row 0

// LIF-AdEx parameters (all defaults from reference)
#define TAU_SYN_INV   0.5f
#define TAU_MEM_INV   0.5f
#define V_TH          1.0f
#define V_PEAK        30.0f
#define INHIBITION    (-5.0f)

// Winner key: upper 32 bits = float bits of v_before (always positive when
// spiked, so raw bits are order-preserving); lower 32 bits = 0xFFFFFFFF - col
// so atomicMax picks the LOWEST column on value ties (jnp.argmax semantics).
// key == 0  <=>  no spike in row 0.
__device__ unsigned long long g_winner_key;

__global__ void k_init() {
    if (threadIdx.x == 0) g_winner_key = 0ULL;
}

// Shared elementwise step — must be arithmetically identical in both kernels
// so the spike decision for row 0 agrees between the reduction and main pass.
__device__ __forceinline__ void lif_step(float x, float v, float i, float w,
                                         float& z, float& v_out, float& i_new,
                                         float& w_new, float& v_before) {
    i_new = fmaf(TAU_SYN_INV, x - i, i);                 // i + 0.5*(x - i)
    float e = __expf(v - V_TH);                          // delta_t * exp((v - v_th)/delta_t), delta_t=1
    float s = e + i_new - w - v;                         // -(v - v_rest) + e + i_new - w
    float vn = fmaf(TAU_MEM_INV, s, v);                  // v + 0.5*s
    w_new = 0.5f * w;                                    // w + 0.5*(0 - w)  (a_param=0)
    v_before = vn;
    bool spike = (vn >= V_PEAK);
    z = spike ? 1.0f : 0.0f;
    v_out = spike ? 0.0f : vn;                           // v_reset = 0; b_param = 0 -> w unchanged on spike
}

// Row-0 reduction: find (max v_before among spiked, lowest index on ties).
// Reads only row 0 (1 MB total) — negligible cost.
__global__ void k_row0_reduce(const float4* __restrict__ x,
                              const float4* __restrict__ v,
                              const float4* __restrict__ i,
                              const float4* __restrict__ w) {
    int t = blockIdx.x * blockDim.x + threadIdx.x;       // 0 .. N4-1
    if (t >= N4) return;

    float4 xf = x[t], vf = v[t], if4 = i[t], wf = w[t];
    float xs[4] = {xf.x, xf.y, xf.z, xf.w};
    float vs[4] = {vf.x, vf.y, vf.z, vf.w};
    float is[4] = {if4.x, if4.y, if4.z, if4.w};
    float ws[4] = {wf.x, wf.y, wf.z, wf.w};

    unsigned long long best = 0ULL;
#pragma unroll
    for (int k = 0; k < 4; k++) {
        float z, vo, in, wn, vb;
        lif_step(xs[k], vs[k], is[k], ws[k], z, vo, in, wn, vb);
        if (vb >= V_PEAK) {
            unsigned col = (unsigned)(t * 4 + k);
            unsigned long long key =
                ((unsigned long long)__float_as_uint(vb) << 32) |
                (unsigned long long)(0xFFFFFFFFu - col);
            if (key > best) best = key;
        }
    }

    // Warp-level max reduction, then one atomic per warp (only if spiked).
#pragma unroll
    for (int o = 16; o > 0; o >>= 1) {
        unsigned long long other = __shfl_down_sync(0xFFFFFFFFu, best, o);
        if (other > best) best = other;
    }
    if ((threadIdx.x & 31) == 0 && best != 0ULL) {
        atomicMax(&g_winner_key, best);
    }
}

// Main elementwise pass, float4-vectorized. Row-0 threads apply the
// winner-take-all inhibition using the reduced key.
__global__ void __launch_bounds__(256)
k_main(const float4* __restrict__ x,
       const float4* __restrict__ v,
       const float4* __restrict__ i,
       const float4* __restrict__ w,
       float4* __restrict__ out) {
    int t = blockIdx.x * blockDim.x + threadIdx.x;       // 0 .. BN4-1
    if (t >= BN4) return;

    float4 xf = x[t], vf = v[t], if4 = i[t], wf = w[t];
    float xs[4] = {xf.x, xf.y, xf.z, xf.w};
    float vs[4] = {vf.x, vf.y, vf.z, vf.w};
    float is[4] = {if4.x, if4.y, if4.z, if4.w};
    float ws[4] = {wf.x, wf.y, wf.z, wf.w};

    float zo[4], vo[4], io[4], wo[4];
#pragma unroll
    for (int k = 0; k < 4; k++) {
        float vb;
        lif_step(xs[k], vs[k], is[k], ws[k], zo[k], vo[k], io[k], wo[k], vb);
    }

    // Winner-take-all lateral inhibition on batch row 0 only.
    if (t < N4) {
        unsigned long long key = g_winner_key;
        if (key != 0ULL) {                                // any_spike0
            unsigned winner = 0xFFFFFFFFu - (unsigned)(key & 0xFFFFFFFFull);
            int base = t * 4;
#pragma unroll
            for (int k = 0; k < 4; k++) {
                if ((unsigned)(base + k) != winner) {     // inhibit everyone but the winner
                    vo[k] = INHIBITION;
                    wo[k] = 0.0f;
                }
            }
        }
    }

    out[t]            = make_float4(zo[0], zo[1], zo[2], zo[3]);
    out[BN4 + t]      = make_float4(vo[0], vo[1], vo[2], vo[3]);
    out[2 * BN4 + t]  = make_float4(io[0], io[1], io[2], io[3]);
    out[3 * BN4 + t]  = make_float4(wo[0], wo[1], wo[2], wo[3]);
}

extern "C" void kernel_launch(void* const* d_in, const int* in_sizes, int n_in,
                              void* d_out, int out_size) {
    const float4* x = (const float4*)d_in[0];
    const float4* v = (const float4*)d_in[1];
    const float4* i = (const float4*)d_in[2];
    const float4* w = (const float4*)d_in[3];
    float4* out = (float4*)d_out;

    k_init<<<1, 32>>>();
    k_row0_reduce<<<(N4 + 255) / 256, 256>>>(x, v, i, w);
    k_main<<<(BN4 + 255) / 256, 256>>>(x, v, i, w, out);
}